// round 17
// baseline (speedup 1.0000x reference)
#include <cuda_runtime.h>
#include <cuda_bf16.h>

#define N_BATCH 4096
#define T_SEQ   200

typedef __nv_bfloat16  bf16;
typedef __nv_bfloat162 bf162;

// ================= device globals (split bf16 weights) =================
__device__ __align__(16) bf16 g_w1h[512 * 128],  g_w1l[512 * 128];
__device__ __align__(16) bf16 g_w2h[256 * 512],  g_w2l[256 * 512];
__device__ __align__(16) bf16 g_w3h[128 * 256],  g_w3l[128 * 256];

// ================= smem map (bytes) =================
// A (pooled, split): 32 rows x 272B; hi at 0, lo at +8704
#define A_OFF     0
#define A_STRIDE  272
#define A_LO      8704
// h1 (split): 32 rows x 1040B; hi at H1_OFF, lo at +33280
#define H1_OFF    17408
#define H1_STRIDE 1040
#define H1_LO     33280
// h2 (split): 32 rows x 528B; hi at H2_OFF, lo at +16896
#define H2_OFF    83968
#define H2_STRIDE 528
#define H2_LO     16896
// B staging: 2 buffers x (128 rows x 80B hi + same lo) = 2 x 20480
#define BST_OFF   117760
#define BBUF      20480
// h3 fp32 overlay on B staging (L3 epilogue, staging drained)
#define H3_OFF    117760
#define SMEM_BYTES 158720

// ================= helpers =================
__device__ __forceinline__ unsigned smem_u32(const void* p) {
    unsigned a;
    asm("{ .reg .u64 t; cvta.to.shared.u64 t, %1; cvt.u32.u64 %0, t; }" : "=r"(a) : "l"(p));
    return a;
}
__device__ __forceinline__ void cp16(unsigned dst, const void* src) {
    asm volatile("cp.async.ca.shared.global [%0], [%1], 16;\n" :: "r"(dst), "l"(src));
}
__device__ __forceinline__ void cp_commit() { asm volatile("cp.async.commit_group;\n"); }

__device__ __forceinline__ void ldsm4(unsigned r[4], unsigned addr) {
    asm volatile("ldmatrix.sync.aligned.m8n8.x4.shared.b16 {%0,%1,%2,%3}, [%4];"
                 : "=r"(r[0]), "=r"(r[1]), "=r"(r[2]), "=r"(r[3]) : "r"(addr));
}
__device__ __forceinline__ void mma16816(float c[4], const unsigned a[4], const unsigned b[2]) {
    asm volatile("mma.sync.aligned.m16n8k16.row.col.f32.bf16.bf16.f32 "
                 "{%0,%1,%2,%3}, {%4,%5,%6,%7}, {%8,%9}, {%0,%1,%2,%3};"
                 : "+f"(c[0]), "+f"(c[1]), "+f"(c[2]), "+f"(c[3])
                 : "r"(a[0]), "r"(a[1]), "r"(a[2]), "r"(a[3]), "r"(b[0]), "r"(b[1]));
}
__device__ __forceinline__ void split2(float v, bf16& h, bf16& l) {
    h = __float2bfloat16(v);
    l = __float2bfloat16(v - __bfloat162float(h));
}

// ================= 0) prep: weight split only =================
__global__ void prep_kernel(const float* __restrict__ W1,
                            const float* __restrict__ W2,
                            const float* __restrict__ W3) {
    int idx = blockIdx.x * blockDim.x + threadIdx.x;
    if (idx < 65536) {
        bf16 h, l; split2(W1[idx], h, l);
        g_w1h[idx] = h; g_w1l[idx] = l;
    } else if (idx < 65536 + 131072) {
        int i2 = idx - 65536;
        bf16 h, l; split2(W2[i2], h, l);
        g_w2h[i2] = h; g_w2l[i2] = l;
    } else if (idx < 65536 + 131072 + 32768) {
        int i3 = idx - 65536 - 131072;
        bf16 h, l; split2(W3[i3], h, l);
        g_w3h[i3] = h; g_w3l[i3] = l;
    }
}

// ================= B chunk staging (512 threads: 1 cp16 hi + 1 lo each) =================
template<int K>
__device__ __forceinline__ void stage_b(unsigned sb, int buf,
        const bf16* Bh, const bf16* Bl, int n0, int kc, int tid) {
    unsigned dst0 = sb + BST_OFF + (unsigned)buf * BBUF;
    int r = tid >> 2, ch = tid & 3;                 // r<128, ch<4
    unsigned doff = (unsigned)(r * 80 + ch * 16);
    long boff = (long)(n0 + r) * K + kc * 32 + ch * 8;
    cp16(dst0 +         doff, Bh + boff);
    cp16(dst0 + 10240 + doff, Bl + boff);
    cp_commit();
}

// one 32-k chunk, warp tile 16x16: wm = wid&1, wn = wid>>1
__device__ __forceinline__ void chunk_mma(unsigned sb, unsigned abase, int astride,
        unsigned alo, int kc, int buf, unsigned b_row_off, int wm,
        float c[2][4], int lane) {
    unsigned bbase = sb + BST_OFF + (unsigned)buf * BBUF + b_row_off;
    #pragma unroll
    for (int ks = 0; ks < 2; ++ks) {
        unsigned a_h[4], a_l[4];
        unsigned aaddr = abase + (unsigned)((wm * 16 + (lane & 15)) * astride)
                       + (unsigned)(kc * 64 + ks * 32) + ((lane >> 4) << 4);
        ldsm4(a_h, aaddr);
        ldsm4(a_l, aaddr + alo);
        unsigned t[4];
        unsigned b_h[2][2], b_l[2][2];
        ldsm4(t, bbase + ks * 32);
        b_h[0][0] = t[0]; b_h[0][1] = t[1]; b_h[1][0] = t[2]; b_h[1][1] = t[3];
        ldsm4(t, bbase + 10240 + ks * 32);
        b_l[0][0] = t[0]; b_l[0][1] = t[1]; b_l[1][0] = t[2]; b_l[1][1] = t[3];
        #pragma unroll
        for (int ni = 0; ni < 2; ++ni) {
            mma16816(c[ni], a_h, b_h[ni]);
            mma16816(c[ni], a_h, b_l[ni]);
            mma16816(c[ni], a_l, b_h[ni]);
        }
    }
}

// ================= fused pool + MLP: 32 rows per block, 512 threads =================
__global__ void __launch_bounds__(512) mlp_kernel(
        const int*   __restrict__ x,
        const int*   __restrict__ lengths,
        const float* __restrict__ emb,
        const float* __restrict__ b1, const float* __restrict__ b2,
        const float* __restrict__ b3, const float* __restrict__ W4,
        const float* __restrict__ b4, float* __restrict__ out) {
    extern __shared__ __align__(16) unsigned char smem[];
    unsigned sb = smem_u32(smem);
    int tid = threadIdx.x, wid = tid >> 5, lane = tid & 31;
    int m0 = blockIdx.x * 32;

    int wm = wid & 1, wn = wid >> 1;                // warp tile: rows wm*16, cols wn*16
    unsigned b_row_off = (unsigned)((wn * 16 + (lane & 7) + ((lane & 16) >> 1)) * 80
                       + (((lane >> 3) & 1) << 4));
    int g = lane >> 2, tig = lane & 3;

    // ---- prefetch first two B chunks of layer 1 (independent of pooling) ----
    stage_b<128>(sb, 0, g_w1h, g_w1l, 0, 0, tid);
    stage_b<128>(sb, 1, g_w1h, g_w1l, 0, 1, tid);

    // ---- pooling prologue: warp wid pools rows m0 + 2*wid, +1 ----
    {
        const float4* emb4 = (const float4*)emb;
        #pragma unroll
        for (int s = 0; s < 2; ++s) {
            int row = 2 * wid + s;
            const int* xr = x + (long)(m0 + row) * T_SEQ;
            int len = lengths[m0 + row];
            float4 acc = make_float4(0.f, 0.f, 0.f, 0.f);
            int t = 0;
            for (; t + 8 <= len; t += 8) {
                int4 ia = *(const int4*)(xr + t);
                int4 ib = *(const int4*)(xr + t + 4);
                float4 v0 = emb4[ia.x * 32 + lane];
                float4 v1 = emb4[ia.y * 32 + lane];
                float4 v2 = emb4[ia.z * 32 + lane];
                float4 v3 = emb4[ia.w * 32 + lane];
                float4 v4 = emb4[ib.x * 32 + lane];
                float4 v5 = emb4[ib.y * 32 + lane];
                float4 v6 = emb4[ib.z * 32 + lane];
                float4 v7 = emb4[ib.w * 32 + lane];
                acc.x += ((v0.x + v1.x) + (v2.x + v3.x)) + ((v4.x + v5.x) + (v6.x + v7.x));
                acc.y += ((v0.y + v1.y) + (v2.y + v3.y)) + ((v4.y + v5.y) + (v6.y + v7.y));
                acc.z += ((v0.z + v1.z) + (v2.z + v3.z)) + ((v4.z + v5.z) + (v6.z + v7.z));
                acc.w += ((v0.w + v1.w) + (v2.w + v3.w)) + ((v4.w + v5.w) + (v6.w + v7.w));
            }
            for (; t < len; ++t) {
                float4 a = emb4[xr[t] * 32 + lane];
                acc.x += a.x; acc.y += a.y; acc.z += a.z; acc.w += a.w;
            }
            float inv = 1.0f / (float)len;
            float vv[4] = {acc.x * inv, acc.y * inv, acc.z * inv, acc.w * inv};
            bf162 h01, l01, h23, l23;
            split2(vv[0], h01.x, l01.x); split2(vv[1], h01.y, l01.y);
            split2(vv[2], h23.x, l23.x); split2(vv[3], h23.y, l23.y);
            unsigned off = (unsigned)(A_OFF + row * A_STRIDE + 8 * lane);
            *reinterpret_cast<bf162*>(smem + off)            = h01;
            *reinterpret_cast<bf162*>(smem + off + 4)        = h23;
            *reinterpret_cast<bf162*>(smem + off + A_LO)     = l01;
            *reinterpret_cast<bf162*>(smem + off + A_LO + 4) = l23;
        }
    }

    float c[2][4];
    #pragma unroll
    for (int j = 0; j < 2; ++j)
        #pragma unroll
        for (int q = 0; q < 4; ++q) c[j][q] = 0.f;

    // =========== layer 1: K=128 (KC=4), N=512 (NC=4) ===========
    {
        const int KC = 4, T = 16;
        for (int it = 0; it < T; ++it) {
            int nc = it / KC, kc = it % KC;
            if (it + 1 < T) asm volatile("cp.async.wait_group 1;\n");
            else            asm volatile("cp.async.wait_group 0;\n");
            __syncthreads();
            if (it + 2 < T) {
                int nn = (it + 2) / KC, nk = (it + 2) % KC;
                // re-stage buffer (it%2): its reads happened in iteration it-1? No:
                // buffer it%2 is being READ this iteration. Stage (it+2)%2 == it%2!
                // So stage AFTER compute below instead.
            }
            chunk_mma(sb, sb + A_OFF, A_STRIDE, A_LO, kc, it & 1, b_row_off, wm, c, lane);
            if (kc == KC - 1) {
                #pragma unroll
                for (int ni = 0; ni < 2; ++ni) {
                    int col = nc * 128 + wn * 16 + ni * 8 + 2 * tig;
                    float b0v = b1[col], b1v = b1[col + 1];
                    #pragma unroll
                    for (int h = 0; h < 2; ++h) {
                        int row = wm * 16 + g + h * 8;
                        float v0 = fmaxf(c[ni][h * 2 + 0] + b0v, 0.f);
                        float v1 = fmaxf(c[ni][h * 2 + 1] + b1v, 0.f);
                        bf162 hh, ll;
                        split2(v0, hh.x, ll.x);
                        split2(v1, hh.y, ll.y);
                        unsigned off = (unsigned)(H1_OFF + row * H1_STRIDE + col * 2);
                        *reinterpret_cast<bf162*>(smem + off)         = hh;
                        *reinterpret_cast<bf162*>(smem + off + H1_LO) = ll;
                        c[ni][h * 2] = 0.f; c[ni][h * 2 + 1] = 0.f;
                    }
                }
            }
            __syncthreads();
            if (it + 2 < T) {
                int nn = (it + 2) / KC, nk = (it + 2) % KC;
                stage_b<128>(sb, it & 1, g_w1h, g_w1l, nn * 128, nk, tid);
            } else if (it + 2 == T) {
                stage_b<512>(sb, it & 1, g_w2h, g_w2l, 0, 0, tid);   // L2 chunk 0
            } else {
                stage_b<512>(sb, it & 1, g_w2h, g_w2l, 0, 1, tid);   // L2 chunk 1
            }
        }
    }

    // =========== layer 2: K=512 (KC=16), N=256 (NC=2) ===========
    {
        const int KC = 16, T = 32;
        for (int it = 0; it < T; ++it) {
            int nc = it / KC, kc = it % KC;
            if (it + 1 < T) asm volatile("cp.async.wait_group 1;\n");
            else            asm volatile("cp.async.wait_group 0;\n");
            __syncthreads();
            chunk_mma(sb, sb + H1_OFF, H1_STRIDE, H1_LO, kc, it & 1, b_row_off, wm, c, lane);
            if (kc == KC - 1) {
                #pragma unroll
                for (int ni = 0; ni < 2; ++ni) {
                    int col = nc * 128 + wn * 16 + ni * 8 + 2 * tig;
                    float b0v = b2[col], b1v = b2[col + 1];
                    #pragma unroll
                    for (int h = 0; h < 2; ++h) {
                        int row = wm * 16 + g + h * 8;
                        float v0 = fmaxf(c[ni][h * 2 + 0] + b0v, 0.f);
                        float v1 = fmaxf(c[ni][h * 2 + 1] + b1v, 0.f);
                        bf162 hh, ll;
                        split2(v0, hh.x, ll.x);
                        split2(v1, hh.y, ll.y);
                        unsigned off = (unsigned)(H2_OFF + row * H2_STRIDE + col * 2);
                        *reinterpret_cast<bf162*>(smem + off)         = hh;
                        *reinterpret_cast<bf162*>(smem + off + H2_LO) = ll;
                        c[ni][h * 2] = 0.f; c[ni][h * 2 + 1] = 0.f;
                    }
                }
            }
            __syncthreads();
            if (it + 2 < T) {
                int nn = (it + 2) / KC, nk = (it + 2) % KC;
                stage_b<512>(sb, it & 1, g_w2h, g_w2l, nn * 128, nk, tid);
            } else if (it + 2 == T) {
                stage_b<256>(sb, it & 1, g_w3h, g_w3l, 0, 0, tid);
            } else {
                stage_b<256>(sb, it & 1, g_w3h, g_w3l, 0, 1, tid);
            }
        }
    }

    // =========== layer 3: K=256 (KC=8), N=128 ===========
    {
        const int KC = 8;
        for (int kc = 0; kc < KC; ++kc) {
            if (kc + 1 < KC) asm volatile("cp.async.wait_group 1;\n");
            else             asm volatile("cp.async.wait_group 0;\n");
            __syncthreads();
            chunk_mma(sb, sb + H2_OFF, H2_STRIDE, H2_LO, kc, kc & 1, b_row_off, wm, c, lane);
            __syncthreads();
            if (kc + 2 < KC)
                stage_b<256>(sb, kc & 1, g_w3h, g_w3l, 0, kc + 2, tid);
        }
    }
    __syncthreads();   // staging drained -> h3 overlay safe

    // h3 epilogue: fp32 relu to smem [32][130]
    {
        float* h3 = (float*)(smem + H3_OFF);
        #pragma unroll
        for (int ni = 0; ni < 2; ++ni) {
            int col = wn * 16 + ni * 8 + 2 * tig;
            float b0v = b3[col], b1v = b3[col + 1];
            #pragma unroll
            for (int h = 0; h < 2; ++h) {
                int row = wm * 16 + g + h * 8;
                h3[row * 130 + col]     = fmaxf(c[ni][h * 2 + 0] + b0v, 0.f);
                h3[row * 130 + col + 1] = fmaxf(c[ni][h * 2 + 1] + b1v, 0.f);
            }
        }
    }
    __syncthreads();

    // fused layer 4: 32 rows x 2 outputs
    if (tid < 64) {
        const float* h3 = (const float*)(smem + H3_OFF);
        int r = tid >> 1, jo = tid & 1;
        float acc = b4[jo];
        #pragma unroll 8
        for (int k = 0; k < 128; ++k)
            acc += h3[r * 130 + k] * W4[jo * 128 + k];
        out[(m0 + r) * 2 + jo] = acc;
    }
}

// ================= launch =================
extern "C" void kernel_launch(void* const* d_in, const int* in_sizes, int n_in,
                              void* d_out, int out_size) {
    const int*   x       = (const int*)  d_in[0];
    const int*   lengths = (const int*)  d_in[1];
    const float* emb     = (const float*)d_in[2];
    const float* W1      = (const float*)d_in[3];
    const float* b1      = (const float*)d_in[4];
    const float* W2      = (const float*)d_in[5];
    const float* b2      = (const float*)d_in[6];
    const float* W3      = (const float*)d_in[7];
    const float* b3      = (const float*)d_in[8];
    const float* W4      = (const float*)d_in[9];
    const float* b4      = (const float*)d_in[10];
    float* out = (float*)d_out;

    cudaFuncSetAttribute(mlp_kernel, cudaFuncAttributeMaxDynamicSharedMemorySize, SMEM_BYTES);

    prep_kernel<<<(229376 + 255) / 256, 256>>>(W1, W2, W3);
    mlp_kernel<<<128, 512, SMEM_BYTES>>>(x, lengths, emb, b1, b2, b3, W4, b4, out);
}